// round 16
// baseline (speedup 1.0000x reference)
#include <cuda_runtime.h>
#include <cuda_fp16.h>

#define NN 100000
#define NE 3200000
#define FEAT 512
#define HID 16
#define NCLS 7
#define GR 256   // gemm rows per block (128 threads x 2 rows)

// ---------------- scratch (device globals; no allocation) ----------------
__device__ int g_is64;
__device__ int g_cnt[NN];
__device__ int g_row[NN + 1];
__device__ int g_fill[NN];
__device__ int g_bsum[512];
__device__ int g_csr[NE];
__device__ float g_dinv[NN];
__device__ __align__(16) __half g_h1[NN * HID];  // (x@W1)*dinv[src], fp16, 32B/row
__device__ __align__(16) __half g_h2[NN * 8];    // layer-2 feats*dinv[src], fp16, 16B/row

// ---------------- helpers ----------------
__device__ __forceinline__ unsigned long long pack2(float x) {
    unsigned long long r;
    asm("mov.b64 %0,{%1,%1};" : "=l"(r) : "f"(x));
    return r;
}
__device__ __forceinline__ void ffma2(unsigned long long& d, unsigned long long a,
                                      unsigned long long b) {
    asm("fma.rn.f32x2 %0,%1,%2,%0;" : "+l"(d) : "l"(a), "l"(b));
}
__device__ __forceinline__ float2 unpack2(unsigned long long v) {
    float2 r;
    asm("mov.b64 {%0,%1},%2;" : "=f"(r.x), "=f"(r.y) : "l"(v));
    return r;
}
__device__ __forceinline__ void acc_u4(float2* acc, uint4 u) {
    const __half2* h = (const __half2*)&u;
#pragma unroll
    for (int j = 0; j < 4; j++) {
        float2 f = __half22float2(h[j]);
        acc[j].x += f.x;
        acc[j].y += f.y;
    }
}

// ---------------- setup: zero counters + dtype probe (warp 0 of block 0) ----------------
__global__ void k_setup(const long long* __restrict__ ei, int e, int n) {
    int i = blockIdx.x * blockDim.x + threadIdx.x;
    if (i < n) g_cnt[i] = 0;
    if (blockIdx.x == 0 && threadIdx.x < 32) {
        int bad = 0;
        for (int j = 0; j < 64; j++) {
            int idx = threadIdx.x * 64 + j;
            if (idx < e) {
                long long v = ei[idx];
                if (v < 0 || v >= NN) bad = 1;
            }
        }
        unsigned m = __ballot_sync(0xffffffffu, bad);
        if (threadIdx.x == 0) g_is64 = (m == 0) ? 1 : 0;
    }
}

__global__ void k_count(const void* __restrict__ ei, int e) {
    int i = blockIdx.x * blockDim.x + threadIdx.x;
    if (i >= e) return;
    int d;
    if (g_is64) d = (int)((const long long*)ei)[e + i];
    else        d = ((const int*)ei)[e + i];
    d = ((unsigned)d < NN) ? d : 0;
    atomicAdd(&g_cnt[d], 1);
}

// ---------------- CSR build: scan (+dinv) + fill ----------------
__global__ __launch_bounds__(512) void k_scan1(int n) {
    __shared__ int sh[512];
    int t = threadIdx.x;
    int g = blockIdx.x * 512 + t;
    int v = (g < n) ? g_cnt[g] : 0;
    sh[t] = v;
    __syncthreads();
#pragma unroll
    for (int off = 1; off < 512; off <<= 1) {
        int a = (t >= off) ? sh[t - off] : 0;
        __syncthreads();
        sh[t] += a;
        __syncthreads();
    }
    if (g < n) {
        g_row[g] = sh[t] - v;
        g_dinv[g] = rsqrtf(1.0f + (float)v);
    }
    if (t == 511) g_bsum[blockIdx.x] = sh[511];
}

__global__ __launch_bounds__(512) void k_scan2(int nb) {
    __shared__ int sh[512];
    int t = threadIdx.x;
    int v = (t < nb) ? g_bsum[t] : 0;
    sh[t] = v;
    __syncthreads();
#pragma unroll
    for (int off = 1; off < 512; off <<= 1) {
        int a = (t >= off) ? sh[t - off] : 0;
        __syncthreads();
        sh[t] += a;
        __syncthreads();
    }
    if (t < nb) g_bsum[t] = sh[t] - v;
}

__global__ __launch_bounds__(512) void k_scan3(int n, int e) {
    int g = blockIdx.x * 512 + threadIdx.x;
    if (g < n) {
        int r = g_row[g] + g_bsum[blockIdx.x];
        g_row[g] = r;
        g_fill[g] = r;
    }
    if (g == 0) g_row[n] = e;
}

__global__ void k_fill(const void* __restrict__ ei, int e) {
    int i = blockIdx.x * blockDim.x + threadIdx.x;
    if (i >= e) return;
    int s, d;
    if (g_is64) {
        const long long* p = (const long long*)ei;
        s = (int)p[i];
        d = (int)p[e + i];
    } else {
        const int* p = (const int*)ei;
        s = p[i];
        d = p[e + i];
    }
    s = ((unsigned)s < NN) ? s : 0;
    d = ((unsigned)d < NN) ? d : 0;
    int pos = atomicAdd(&g_fill[d], 1);
    g_csr[pos] = s;
}

// ---------------- GEMM1: g_h1 = fp16((x @ W1) * dinv) ----------------
// W1 fully SMEM-resident (32KB, loaded once). x streamed global->regs with
// distance-2 prefetch. 2 rows/thread, 128 threads. One syncthreads total.
__global__ __launch_bounds__(128) void k_gemm1(const float* __restrict__ x,
                                               const float* __restrict__ W1, int n) {
    __shared__ __align__(16) float sW[FEAT * HID];  // 32KB: W[k][c]
    int tid = threadIdx.x;
    int row0 = blockIdx.x * GR;
    int rA = row0 + tid;
    int rB = row0 + tid + 128;
    bool vA = rA < n, vB = rB < n;

    // load all of W1 once (128 threads x 16 float4)
#pragma unroll
    for (int it = 0; it < 16; it++)
        ((float4*)sW)[tid + 128 * it] = ((const float4*)W1)[tid + 128 * it];
    __syncthreads();

    unsigned long long acc[2][8];
#pragma unroll
    for (int r = 0; r < 2; r++)
#pragma unroll
        for (int p = 0; p < 8; p++) acc[r][p] = 0ull;

    const float4* xA = (const float4*)(x + (size_t)rA * FEAT);
    const float4* xB = (const float4*)(x + (size_t)rB * FEAT);
    const float4 z4 = make_float4(0.f, 0.f, 0.f, 0.f);

    // distance-2 ring prefetch: 4 LDG.128 in flight per thread
    float4 bufA[2], bufB[2];
    bufA[0] = vA ? xA[0] : z4;
    bufB[0] = vB ? xB[0] : z4;
    bufA[1] = vA ? xA[1] : z4;
    bufB[1] = vB ? xB[1] : z4;

    for (int kc = 0; kc < FEAT / 4; kc++) {  // 128 chunks of 4 k-steps
        int slot = kc & 1;
        float4 a = bufA[slot];
        float4 b = bufB[slot];
        if (kc + 2 < FEAT / 4) {
            bufA[slot] = vA ? xA[kc + 2] : z4;
            bufB[slot] = vB ? xB[kc + 2] : z4;
        }
        float as[4] = {a.x, a.y, a.z, a.w};
        float bs[4] = {b.x, b.y, b.z, b.w};
#pragma unroll
        for (int j = 0; j < 4; j++) {
            const float4* wp4 = (const float4*)(sW + (kc * 4 + j) * 16);
            unsigned long long w[8];
#pragma unroll
            for (int q = 0; q < 4; q++) {
                float4 wv = wp4[q];  // broadcast LDS.128 (all lanes same addr)
                w[2 * q] = *(unsigned long long*)&wv.x;
                w[2 * q + 1] = *(unsigned long long*)&wv.z;
            }
            unsigned long long xa = pack2(as[j]);
            unsigned long long xb = pack2(bs[j]);
#pragma unroll
            for (int p = 0; p < 8; p++) {
                ffma2(acc[0][p], xa, w[p]);
                ffma2(acc[1][p], xb, w[p]);
            }
        }
    }

#pragma unroll
    for (int r = 0; r < 2; r++) {
        int g = row0 + tid + 128 * r;
        if (g < n) {
            float d = g_dinv[g];
            __half2 o[8];
#pragma unroll
            for (int p = 0; p < 8; p++) {
                float2 u = unpack2(acc[r][p]);
                o[p] = __floats2half2_rn(u.x * d, u.y * d);
            }
            uint4* hp = (uint4*)(g_h1 + (size_t)g * HID);
            hp[0] = *(uint4*)&o[0];
            hp[1] = *(uint4*)&o[4];
        }
    }
}

// ---------------- agg1 + layer2 fused (fp16 gathers, 32B/edge) ----------------
__global__ __launch_bounds__(256) void k_agg1(const float* __restrict__ W2,
                                              const float* __restrict__ b1, int n) {
    __shared__ float sW2[HID * NCLS];
    __shared__ float sb1[HID];
    if (threadIdx.x < HID * NCLS) sW2[threadIdx.x] = W2[threadIdx.x];
    if (threadIdx.x < HID) sb1[threadIdx.x] = b1[threadIdx.x];
    __syncthreads();
    int lane = threadIdx.x & 31;
    int node = blockIdx.x * 8 + (threadIdx.x >> 5);
    if (node >= n) return;
    int p = lane & 1;    // which 16B half of the 32B row
    int es = lane >> 1;  // edge slot 0..15
    int r0 = g_row[node], r1 = g_row[node + 1];
    const int* __restrict__ csr = g_csr;
    const __half* __restrict__ h1p = g_h1 + p * 8;
    float2 acc[4] = {{0.f,0.f},{0.f,0.f},{0.f,0.f},{0.f,0.f}};
    int k = r0 + es;
    for (; k + 16 < r1; k += 32) {
        int s0 = csr[k];
        int s1 = csr[k + 16];
        uint4 u0 = *(const uint4*)(h1p + (size_t)s0 * HID);
        uint4 u1 = *(const uint4*)(h1p + (size_t)s1 * HID);
        acc_u4(acc, u0);
        acc_u4(acc, u1);
    }
    for (; k < r1; k += 16) {
        int s = csr[k];
        uint4 u = *(const uint4*)(h1p + (size_t)s * HID);
        acc_u4(acc, u);
    }
#pragma unroll
    for (int off = 2; off < 32; off <<= 1) {
#pragma unroll
        for (int j = 0; j < 4; j++) {
            acc[j].x += __shfl_xor_sync(0xffffffffu, acc[j].x, off);
            acc[j].y += __shfl_xor_sync(0xffffffffu, acc[j].y, off);
        }
    }
    {   // self-term
        uint4 u = *(const uint4*)(h1p + (size_t)node * HID);
        acc_u4(acc, u);
    }
    float v[HID];
#pragma unroll
    for (int j = 0; j < 4; j++) {
        v[2 * j + 0] = __shfl_sync(0xffffffffu, acc[j].x, 0);
        v[2 * j + 1] = __shfl_sync(0xffffffffu, acc[j].y, 0);
        v[8 + 2 * j + 0] = __shfl_sync(0xffffffffu, acc[j].x, 1);
        v[8 + 2 * j + 1] = __shfl_sync(0xffffffffu, acc[j].y, 1);
    }
    float d = g_dinv[node];
#pragma unroll
    for (int j = 0; j < HID; j++) v[j] = fmaxf(fmaf(v[j], d, sb1[j]), 0.0f);
    float h[4];
    if (lane < 2) {
#pragma unroll
        for (int c = 0; c < 4; c++) {
            int cc = lane * 4 + c;
            float s = 0.0f;
            if (cc < NCLS) {
#pragma unroll
                for (int j = 0; j < HID; j++) s += v[j] * sW2[j * NCLS + cc];
                h[c] = s * d;
            } else h[c] = 0.0f;
        }
    } else { h[0] = h[1] = h[2] = h[3] = 0.0f; }
    float h4 = __shfl_sync(0xffffffffu, h[0], 1);
    float h5 = __shfl_sync(0xffffffffu, h[1], 1);
    float h6 = __shfl_sync(0xffffffffu, h[2], 1);
    if (lane == 0) {
        __half2 o[4];
        o[0] = __floats2half2_rn(h[0], h[1]);
        o[1] = __floats2half2_rn(h[2], h[3]);
        o[2] = __floats2half2_rn(h4, h5);
        o[3] = __floats2half2_rn(h6, 0.0f);
        *(uint4*)(g_h2 + (size_t)node * 8) = *(uint4*)&o[0];
    }
}

// ---------------- agg2 + bias + log_softmax fused (fp16 gathers, 16B/edge) ----------------
__global__ __launch_bounds__(256) void k_agg2(const float* __restrict__ b2,
                                              float* __restrict__ out, int n) {
    __shared__ float sb2[NCLS];
    if (threadIdx.x < NCLS) sb2[threadIdx.x] = b2[threadIdx.x];
    __syncthreads();
    int lane = threadIdx.x & 31;
    int node = blockIdx.x * 8 + (threadIdx.x >> 5);
    if (node >= n) return;
    int r0 = g_row[node], r1 = g_row[node + 1];
    const int* __restrict__ csr = g_csr;
    float2 acc[4] = {{0.f,0.f},{0.f,0.f},{0.f,0.f},{0.f,0.f}};
    int k = r0 + lane;
    for (; k + 32 < r1; k += 64) {
        int s0 = csr[k];
        int s1 = csr[k + 32];
        uint4 u0 = *(const uint4*)(g_h2 + (size_t)s0 * 8);
        uint4 u1 = *(const uint4*)(g_h2 + (size_t)s1 * 8);
        acc_u4(acc, u0);
        acc_u4(acc, u1);
    }
    for (; k < r1; k += 32) {
        int s = csr[k];
        uint4 u = *(const uint4*)(g_h2 + (size_t)s * 8);
        acc_u4(acc, u);
    }
    if (lane == 0) {
        uint4 u = *(const uint4*)(g_h2 + (size_t)node * 8);
        acc_u4(acc, u);
    }
#pragma unroll
    for (int off = 1; off < 32; off <<= 1) {
#pragma unroll
        for (int j = 0; j < 4; j++) {
            acc[j].x += __shfl_xor_sync(0xffffffffu, acc[j].x, off);
            acc[j].y += __shfl_xor_sync(0xffffffffu, acc[j].y, off);
        }
    }
    if (lane == 0) {
        float d = g_dinv[node];
        float z[NCLS];
        z[0] = fmaf(acc[0].x, d, sb2[0]);
        z[1] = fmaf(acc[0].y, d, sb2[1]);
        z[2] = fmaf(acc[1].x, d, sb2[2]);
        z[3] = fmaf(acc[1].y, d, sb2[3]);
        z[4] = fmaf(acc[2].x, d, sb2[4]);
        z[5] = fmaf(acc[2].y, d, sb2[5]);
        z[6] = fmaf(acc[3].x, d, sb2[6]);
        float m = z[0];
#pragma unroll
        for (int c = 1; c < NCLS; c++) m = fmaxf(m, z[c]);
        float s = 0.0f;
#pragma unroll
        for (int c = 0; c < NCLS; c++) s += __expf(z[c] - m);
        float l = logf(s);
        float* op = out + (size_t)node * NCLS;
#pragma unroll
        for (int c = 0; c < NCLS; c++) op[c] = z[c] - m - l;
    }
}

// ---------------- launcher ----------------
extern "C" void kernel_launch(void* const* d_in, const int* in_sizes, int n_in,
                              void* d_out, int out_size) {
    const float* x = (const float*)d_in[0];
    const void* ei = d_in[1];
    const float* W1 = (const float*)d_in[2];
    const float* b1 = (const float*)d_in[3];
    const float* W2 = (const float*)d_in[4];
    const float* b2 = (const float*)d_in[5];
    float* out = (float*)d_out;

    int n = in_sizes[0] / FEAT;  // 100000
    int e = in_sizes[1] / 2;     // 3200000
    int nb = (n + 511) / 512;    // 196

    k_setup<<<(n + 255) / 256, 256>>>((const long long*)ei, e, n);  // 0
    k_count<<<(e + 255) / 256, 256>>>(ei, e);                        // 1
    k_scan1<<<nb, 512>>>(n);                                         // 2
    k_gemm1<<<(n + GR - 1) / GR, 128>>>(x, W1, n);                   // 3 (profiled slot)
    k_scan2<<<1, 512>>>(nb);                                         // 4
    k_scan3<<<nb, 512>>>(n, e);                                      // 5
    k_fill<<<(e + 255) / 256, 256>>>(ei, e);                         // 6
    k_agg1<<<(n + 7) / 8, 256>>>(W2, b1, n);                         // 7
    k_agg2<<<(n + 7) / 8, 256>>>(b2, out, n);                        // 8
}

// round 17
// speedup vs baseline: 1.6242x; 1.6242x over previous
#include <cuda_runtime.h>
#include <cuda_fp16.h>

#define NN 100000
#define NE 3200000
#define FEAT 512
#define HID 16
#define NCLS 7
#define GR 256   // gemm rows per block (128 threads x 2 rows)

// ---------------- scratch (device globals; no allocation) ----------------
__device__ int g_is64;
__device__ int g_cnt[NN];
__device__ int g_row[NN + 1];
__device__ int g_fill[NN];
__device__ int g_bsum[512];
__device__ int g_csr[NE];
__device__ float g_dinv[NN];
__device__ __align__(16) __half g_h1[NN * HID];  // x@W1 (unscaled until k_scale), fp16
__device__ __align__(16) __half g_h2[NN * 8];    // layer-2 feats*dinv[src], fp16

// ---------------- streams/events for fork-join (created pre-checkpoint) ----------------
static cudaStream_t g_s2 = nullptr;
static cudaEvent_t g_evF = nullptr, g_evJ = nullptr;
namespace {
struct InitStreams {
    InitStreams() {
        if (cudaStreamCreateWithFlags(&g_s2, cudaStreamNonBlocking) != cudaSuccess) g_s2 = nullptr;
        if (cudaEventCreateWithFlags(&g_evF, cudaEventDisableTiming) != cudaSuccess) g_evF = nullptr;
        if (cudaEventCreateWithFlags(&g_evJ, cudaEventDisableTiming) != cudaSuccess) g_evJ = nullptr;
    }
};
InitStreams g_initStreams;
}

// ---------------- helpers ----------------
__device__ __forceinline__ unsigned long long pack2(float x) {
    unsigned long long r;
    asm("mov.b64 %0,{%1,%1};" : "=l"(r) : "f"(x));
    return r;
}
__device__ __forceinline__ void ffma2(unsigned long long& d, unsigned long long a,
                                      unsigned long long b) {
    asm("fma.rn.f32x2 %0,%1,%2,%0;" : "+l"(d) : "l"(a), "l"(b));
}
__device__ __forceinline__ float2 unpack2(unsigned long long v) {
    float2 r;
    asm("mov.b64 {%0,%1},%2;" : "=f"(r.x), "=f"(r.y) : "l"(v));
    return r;
}
__device__ __forceinline__ void acc_u4(float2* acc, uint4 u) {
    const __half2* h = (const __half2*)&u;
#pragma unroll
    for (int j = 0; j < 4; j++) {
        float2 f = __half22float2(h[j]);
        acc[j].x += f.x;
        acc[j].y += f.y;
    }
}

// ---------------- setup: zero counters + dtype probe (warp 0 of block 0) ----------------
__global__ void k_setup(const long long* __restrict__ ei, int e, int n) {
    int i = blockIdx.x * blockDim.x + threadIdx.x;
    if (i < n) g_cnt[i] = 0;
    if (blockIdx.x == 0 && threadIdx.x < 32) {
        int bad = 0;
        for (int j = 0; j < 64; j++) {
            int idx = threadIdx.x * 64 + j;
            if (idx < e) {
                long long v = ei[idx];
                if (v < 0 || v >= NN) bad = 1;
            }
        }
        unsigned m = __ballot_sync(0xffffffffu, bad);
        if (threadIdx.x == 0) g_is64 = (m == 0) ? 1 : 0;
    }
}

__global__ void k_count(const void* __restrict__ ei, int e) {
    int i = blockIdx.x * blockDim.x + threadIdx.x;
    if (i >= e) return;
    int d;
    if (g_is64) d = (int)((const long long*)ei)[e + i];
    else        d = ((const int*)ei)[e + i];
    d = ((unsigned)d < NN) ? d : 0;
    atomicAdd(&g_cnt[d], 1);
}

// ---------------- CSR build: scan (+dinv) + fill ----------------
__global__ __launch_bounds__(512) void k_scan1(int n) {
    __shared__ int sh[512];
    int t = threadIdx.x;
    int g = blockIdx.x * 512 + t;
    int v = (g < n) ? g_cnt[g] : 0;
    sh[t] = v;
    __syncthreads();
#pragma unroll
    for (int off = 1; off < 512; off <<= 1) {
        int a = (t >= off) ? sh[t - off] : 0;
        __syncthreads();
        sh[t] += a;
        __syncthreads();
    }
    if (g < n) {
        g_row[g] = sh[t] - v;
        g_dinv[g] = rsqrtf(1.0f + (float)v);
    }
    if (t == 511) g_bsum[blockIdx.x] = sh[511];
}

__global__ __launch_bounds__(512) void k_scan2(int nb) {
    __shared__ int sh[512];
    int t = threadIdx.x;
    int v = (t < nb) ? g_bsum[t] : 0;
    sh[t] = v;
    __syncthreads();
#pragma unroll
    for (int off = 1; off < 512; off <<= 1) {
        int a = (t >= off) ? sh[t - off] : 0;
        __syncthreads();
        sh[t] += a;
        __syncthreads();
    }
    if (t < nb) g_bsum[t] = sh[t] - v;
}

__global__ __launch_bounds__(512) void k_scan3(int n, int e) {
    int g = blockIdx.x * 512 + threadIdx.x;
    if (g < n) {
        int r = g_row[g] + g_bsum[blockIdx.x];
        g_row[g] = r;
        g_fill[g] = r;
    }
    if (g == 0) g_row[n] = e;
}

__global__ void k_fill(const void* __restrict__ ei, int e) {
    int i = blockIdx.x * blockDim.x + threadIdx.x;
    if (i >= e) return;
    int s, d;
    if (g_is64) {
        const long long* p = (const long long*)ei;
        s = (int)p[i];
        d = (int)p[e + i];
    } else {
        const int* p = (const int*)ei;
        s = p[i];
        d = p[e + i];
    }
    s = ((unsigned)s < NN) ? s : 0;
    d = ((unsigned)d < NN) ? d : 0;
    int pos = atomicAdd(&g_fill[d], 1);
    g_csr[pos] = s;
}

// ---------------- GEMM1 (R14 structure): g_h1 = fp16(x @ W1), UNSCALED ----------------
// No inputs besides x, W1 -> runs concurrently with the CSR build.
__global__ __launch_bounds__(128) void k_gemm1(const float* __restrict__ x,
                                               const float* __restrict__ W1, int n) {
    __shared__ __align__(16) float sW[2][16 * 16];
    __shared__ float sX[2][GR * 17];
    int tid = threadIdx.x;
    int row0 = blockIdx.x * GR;

    unsigned long long acc[2][8];
#pragma unroll
    for (int r = 0; r < 2; r++)
#pragma unroll
        for (int p = 0; p < 8; p++) acc[r][p] = 0ull;

    float4 rx[8];
    float2 rw;

    rw = ((const float2*)(W1 + 0))[tid];
#pragma unroll
    for (int it = 0; it < 8; it++) {
        int idx = tid + 128 * it;
        int row = idx >> 2, c4 = idx & 3;
        int g = row0 + row;
        rx[it] = (g < n) ? *(const float4*)(x + (size_t)g * FEAT + c4 * 4)
                         : make_float4(0.f, 0.f, 0.f, 0.f);
    }
    {
        ((float2*)sW[0])[tid] = rw;
#pragma unroll
        for (int it = 0; it < 8; it++) {
            int idx = tid + 128 * it;
            int row = idx >> 2, c4 = idx & 3;
            float* sp = &sX[0][row * 17 + c4 * 4];
            sp[0] = rx[it].x; sp[1] = rx[it].y; sp[2] = rx[it].z; sp[3] = rx[it].w;
        }
    }
    __syncthreads();

    for (int kc = 0; kc < 32; kc++) {
        int cur = kc & 1;
        if (kc + 1 < 32) {
            rw = ((const float2*)(W1 + (kc + 1) * 256))[tid];
#pragma unroll
            for (int it = 0; it < 8; it++) {
                int idx = tid + 128 * it;
                int row = idx >> 2, c4 = idx & 3;
                int g = row0 + row;
                rx[it] = (g < n)
                    ? *(const float4*)(x + (size_t)g * FEAT + (kc + 1) * 16 + c4 * 4)
                    : make_float4(0.f, 0.f, 0.f, 0.f);
            }
        }
#pragma unroll
        for (int kk = 0; kk < 16; kk++) {
            unsigned long long w[8];
            const unsigned long long* wp = (const unsigned long long*)(sW[cur] + kk * 16);
#pragma unroll
            for (int p = 0; p < 8; p++) w[p] = wp[p];
#pragma unroll
            for (int r = 0; r < 2; r++) {
                float xv = sX[cur][(tid + 128 * r) * 17 + kk];
                unsigned long long xx = pack2(xv);
#pragma unroll
                for (int p = 0; p < 8; p++) ffma2(acc[r][p], xx, w[p]);
            }
        }
        __syncthreads();
        if (kc + 1 < 32) {
            int nxt = (kc + 1) & 1;
            ((float2*)sW[nxt])[tid] = rw;
#pragma unroll
            for (int it = 0; it < 8; it++) {
                int idx = tid + 128 * it;
                int row = idx >> 2, c4 = idx & 3;
                float* sp = &sX[nxt][row * 17 + c4 * 4];
                sp[0] = rx[it].x; sp[1] = rx[it].y; sp[2] = rx[it].z; sp[3] = rx[it].w;
            }
            __syncthreads();
        }
    }
#pragma unroll
    for (int r = 0; r < 2; r++) {
        int g = row0 + tid + 128 * r;
        if (g < n) {
            __half2 o[8];
#pragma unroll
            for (int p = 0; p < 8; p++) {
                float2 u = unpack2(acc[r][p]);
                o[p] = __floats2half2_rn(u.x, u.y);
            }
            uint4* hp = (uint4*)(g_h1 + (size_t)g * HID);
            hp[0] = *(uint4*)&o[0];
            hp[1] = *(uint4*)&o[4];
        }
    }
}

// ---------------- k_scale: h1[i] *= dinv[i] (join point, ~6.4MB traffic) ----------------
__global__ void k_scale(int n) {
    int i = blockIdx.x * blockDim.x + threadIdx.x;
    if (i >= n) return;
    __half2 d2 = __float2half2_rn(g_dinv[i]);
    uint4* hp = (uint4*)(g_h1 + (size_t)i * HID);
    uint4 a = hp[0], b = hp[1];
    __half2* ha = (__half2*)&a;
    __half2* hb = (__half2*)&b;
#pragma unroll
    for (int j = 0; j < 4; j++) {
        ha[j] = __hmul2(ha[j], d2);
        hb[j] = __hmul2(hb[j], d2);
    }
    hp[0] = a;
    hp[1] = b;
}

// ---------------- agg1 + layer2 fused (fp16 gathers, 32B/edge) ----------------
__global__ __launch_bounds__(256) void k_agg1(const float* __restrict__ W2,
                                              const float* __restrict__ b1, int n) {
    __shared__ float sW2[HID * NCLS];
    __shared__ float sb1[HID];
    if (threadIdx.x < HID * NCLS) sW2[threadIdx.x] = W2[threadIdx.x];
    if (threadIdx.x < HID) sb1[threadIdx.x] = b1[threadIdx.x];
    __syncthreads();
    int lane = threadIdx.x & 31;
    int node = blockIdx.x * 8 + (threadIdx.x >> 5);
    if (node >= n) return;
    int p = lane & 1;
    int es = lane >> 1;
    int r0 = g_row[node], r1 = g_row[node + 1];
    const int* __restrict__ csr = g_csr;
    const __half* __restrict__ h1p = g_h1 + p * 8;
    float2 acc[4] = {{0.f,0.f},{0.f,0.f},{0.f,0.f},{0.f,0.f}};
    int k = r0 + es;
    for (; k + 16 < r1; k += 32) {
        int s0 = csr[k];
        int s1 = csr[k + 16];
        uint4 u0 = *(const uint4*)(h1p + (size_t)s0 * HID);
        uint4 u1 = *(const uint4*)(h1p + (size_t)s1 * HID);
        acc_u4(acc, u0);
        acc_u4(acc, u1);
    }
    for (; k < r1; k += 16) {
        int s = csr[k];
        uint4 u = *(const uint4*)(h1p + (size_t)s * HID);
        acc_u4(acc, u);
    }
#pragma unroll
    for (int off = 2; off < 32; off <<= 1) {
#pragma unroll
        for (int j = 0; j < 4; j++) {
            acc[j].x += __shfl_xor_sync(0xffffffffu, acc[j].x, off);
            acc[j].y += __shfl_xor_sync(0xffffffffu, acc[j].y, off);
        }
    }
    {   // self-term
        uint4 u = *(const uint4*)(h1p + (size_t)node * HID);
        acc_u4(acc, u);
    }
    float v[HID];
#pragma unroll
    for (int j = 0; j < 4; j++) {
        v[2 * j + 0] = __shfl_sync(0xffffffffu, acc[j].x, 0);
        v[2 * j + 1] = __shfl_sync(0xffffffffu, acc[j].y, 0);
        v[8 + 2 * j + 0] = __shfl_sync(0xffffffffu, acc[j].x, 1);
        v[8 + 2 * j + 1] = __shfl_sync(0xffffffffu, acc[j].y, 1);
    }
    float d = g_dinv[node];
#pragma unroll
    for (int j = 0; j < HID; j++) v[j] = fmaxf(fmaf(v[j], d, sb1[j]), 0.0f);
    float h[4];
    if (lane < 2) {
#pragma unroll
        for (int c = 0; c < 4; c++) {
            int cc = lane * 4 + c;
            float s = 0.0f;
            if (cc < NCLS) {
#pragma unroll
                for (int j = 0; j < HID; j++) s += v[j] * sW2[j * NCLS + cc];
                h[c] = s * d;
            } else h[c] = 0.0f;
        }
    } else { h[0] = h[1] = h[2] = h[3] = 0.0f; }
    float h4 = __shfl_sync(0xffffffffu, h[0], 1);
    float h5 = __shfl_sync(0xffffffffu, h[1], 1);
    float h6 = __shfl_sync(0xffffffffu, h[2], 1);
    if (lane == 0) {
        __half2 o[4];
        o[0] = __floats2half2_rn(h[0], h[1]);
        o[1] = __floats2half2_rn(h[2], h[3]);
        o[2] = __floats2half2_rn(h4, h5);
        o[3] = __floats2half2_rn(h6, 0.0f);
        *(uint4*)(g_h2 + (size_t)node * 8) = *(uint4*)&o[0];
    }
}

// ---------------- agg2 + bias + log_softmax fused (fp16 gathers, 16B/edge) ----------------
__global__ __launch_bounds__(256) void k_agg2(const float* __restrict__ b2,
                                              float* __restrict__ out, int n) {
    __shared__ float sb2[NCLS];
    if (threadIdx.x < NCLS) sb2[threadIdx.x] = b2[threadIdx.x];
    __syncthreads();
    int lane = threadIdx.x & 31;
    int node = blockIdx.x * 8 + (threadIdx.x >> 5);
    if (node >= n) return;
    int r0 = g_row[node], r1 = g_row[node + 1];
    const int* __restrict__ csr = g_csr;
    float2 acc[4] = {{0.f,0.f},{0.f,0.f},{0.f,0.f},{0.f,0.f}};
    int k = r0 + lane;
    for (; k + 32 < r1; k += 64) {
        int s0 = csr[k];
        int s1 = csr[k + 32];
        uint4 u0 = *(const uint4*)(g_h2 + (size_t)s0 * 8);
        uint4 u1 = *(const uint4*)(g_h2 + (size_t)s1 * 8);
        acc_u4(acc, u0);
        acc_u4(acc, u1);
    }
    for (; k < r1; k += 32) {
        int s = csr[k];
        uint4 u = *(const uint4*)(g_h2 + (size_t)s * 8);
        acc_u4(acc, u);
    }
    if (lane == 0) {
        uint4 u = *(const uint4*)(g_h2 + (size_t)node * 8);
        acc_u4(acc, u);
    }
#pragma unroll
    for (int off = 1; off < 32; off <<= 1) {
#pragma unroll
        for (int j = 0; j < 4; j++) {
            acc[j].x += __shfl_xor_sync(0xffffffffu, acc[j].x, off);
            acc[j].y += __shfl_xor_sync(0xffffffffu, acc[j].y, off);
        }
    }
    if (lane == 0) {
        float d = g_dinv[node];
        float z[NCLS];
        z[0] = fmaf(acc[0].x, d, sb2[0]);
        z[1] = fmaf(acc[0].y, d, sb2[1]);
        z[2] = fmaf(acc[1].x, d, sb2[2]);
        z[3] = fmaf(acc[1].y, d, sb2[3]);
        z[4] = fmaf(acc[2].x, d, sb2[4]);
        z[5] = fmaf(acc[2].y, d, sb2[5]);
        z[6] = fmaf(acc[3].x, d, sb2[6]);
        float m = z[0];
#pragma unroll
        for (int c = 1; c < NCLS; c++) m = fmaxf(m, z[c]);
        float s = 0.0f;
#pragma unroll
        for (int c = 0; c < NCLS; c++) s += __expf(z[c] - m);
        float l = logf(s);
        float* op = out + (size_t)node * NCLS;
#pragma unroll
        for (int c = 0; c < NCLS; c++) op[c] = z[c] - m - l;
    }
}

// ---------------- launcher ----------------
extern "C" void kernel_launch(void* const* d_in, const int* in_sizes, int n_in,
                              void* d_out, int out_size) {
    const float* x = (const float*)d_in[0];
    const void* ei = d_in[1];
    const float* W1 = (const float*)d_in[2];
    const float* b1 = (const float*)d_in[3];
    const float* W2 = (const float*)d_in[4];
    const float* b2 = (const float*)d_in[5];
    float* out = (float*)d_out;

    int n = in_sizes[0] / FEAT;  // 100000
    int e = in_sizes[1] / 2;     // 3200000
    int nb = (n + 511) / 512;    // 196

    bool par = (g_s2 != nullptr) && (g_evF != nullptr) && (g_evJ != nullptr);

    if (par) {
        // fork: gemm1 on side stream, concurrent with CSR build
        cudaEventRecord(g_evF, 0);
        cudaStreamWaitEvent(g_s2, g_evF, 0);
        k_gemm1<<<(n + GR - 1) / GR, 128, 0, g_s2>>>(x, W1, n);
        cudaEventRecord(g_evJ, g_s2);
    }

    k_setup<<<(n + 255) / 256, 256>>>((const long long*)ei, e, n);
    k_count<<<(e + 255) / 256, 256>>>(ei, e);
    k_scan1<<<nb, 512>>>(n);
    k_scan2<<<1, 512>>>(nb);
    k_scan3<<<nb, 512>>>(n, e);
    k_fill<<<(e + 255) / 256, 256>>>(ei, e);

    if (par) {
        cudaStreamWaitEvent(0, g_evJ, 0);  // join
    } else {
        k_gemm1<<<(n + GR - 1) / GR, 128>>>(x, W1, n);  // sequential fallback
    }

    k_scale<<<(n + 255) / 256, 256>>>(n);
    k_agg1<<<(n + 7) / 8, 256>>>(W2, b1, n);
    k_agg2<<<(n + 7) / 8, 256>>>(b2, out, n);
}